// round 1
// baseline (speedup 1.0000x reference)
#include <cuda_runtime.h>
#include <math.h>

// Kaldi LinearResample 16000 -> 14400, LPF_WIDTH=6.
//   gcd = 1600, up = 9 phases, conv_stride = 10.
//   out[b, 9k+i] = sum_m w[i][m] * x[b, 10k + fi[i] + m]   (x zero outside [0,T))
//   fi[i] = ceil(10 i / 9 - 6.734007) = {-6,-5,-4,-3,-2,-1,0,2,3}
//   Weight depends only on |n|, n = 9*(fi[i]+m) - 10*i, dt = n/144000:
//     w = 0.5*(1+cos(0.0165*pi*|n|)) * sin(0.099*pi*|n|) * 9/(pi*|n|),  |n|<=60
//     w(0) = 14256/16000 = 0.891
//   => 61 distinct weights total (each used <=2x), kept in registers.

#define T_IN        480000
#define TOT_K       48000        // output blocks per row (432000 / 9)
#define UP          9
#define TOT_OUT     (TOT_K * UP) // 432000
#define TILE_K      256          // k-blocks per CTA iteration
#define TILE_F      2576         // staged input floats (>= 10*255+21+6+shift, 16B-multiple)
#define TILES_PER_ROW 188        // ceil(48000/256); last tile nk=128 (exact warps)
#define NCTA        752

__device__ float g_w61[61];

__global__ void sp_weights_kernel() {
    int a = threadIdx.x;
    if (a < 61) {
        double v;
        if (a == 0) {
            v = 14256.0 / 16000.0;   // 2 * lowpass_cutoff / orig_freq
        } else {
            double pa = M_PI * (double)a;
            v = 9.0 * (1.0 + cos(0.0165 * pa)) * sin(0.099 * pa) / (2.0 * M_PI * (double)a);
        }
        g_w61[a] = (float)v;
    }
}

__global__ __launch_bounds__(256, 2)
void sp_resample_kernel(const float* __restrict__ in, float* __restrict__ out, int ntiles) {
    __shared__ float xs[TILE_F];
    __shared__ float os[TILE_K * UP];   // 2304 floats, per-warp transpose buffer

    // 61 distinct filter weights -> registers, loaded once per CTA lifetime.
    float W[61];
#pragma unroll
    for (int a = 0; a < 61; ++a) W[a] = __ldg(&g_w61[a]);

    const int tid  = threadIdx.x;
    const int wid  = tid >> 5;
    const int lane = tid & 31;

    for (int t = blockIdx.x; t < ntiles; t += gridDim.x) {
        const int b  = t / TILES_PER_ROW;
        const int kt = (t - b * TILES_PER_ROW) * TILE_K;
        const int nk = min(TILE_K, TOT_K - kt);    // 256 or 128 (always warp-multiple)
        const float* rowin = in + (size_t)b * T_IN;

        const int gstart = 10 * kt - 6;            // first needed input index (row-local)
        const int g4     = gstart & ~3;            // 16B-aligned base (works for negatives)
        const int shift  = gstart - g4;            // 0..3

        __syncthreads();  // previous tile's xs reads / os reads finished block-wide

        // ---- Stage input tile to smem: coalesced float4, zero outside [0, T_IN) ----
        for (int v = tid; v < TILE_F / 4; v += 256) {
            int g = g4 + 4 * v;
            float4 val;
            if (g >= 0 && g <= T_IN - 4) {
                val = *reinterpret_cast<const float4*>(rowin + g);
            } else {
                val.x = (g + 0 >= 0 && g + 0 < T_IN) ? rowin[g + 0] : 0.0f;
                val.y = (g + 1 >= 0 && g + 1 < T_IN) ? rowin[g + 1] : 0.0f;
                val.z = (g + 2 >= 0 && g + 2 < T_IN) ? rowin[g + 2] : 0.0f;
                val.w = (g + 3 >= 0 && g + 3 < T_IN) ? rowin[g + 3] : 0.0f;
            }
            reinterpret_cast<float4*>(xs)[v] = val;
        }
        __syncthreads();

        // ---- Compute: each thread = one k-block (9 outputs from a 22-float window) ----
        if (tid < nk) {
            float xr[22];
            const int w0 = 10 * tid + shift;       // xs index of x[10k - 6]
#pragma unroll
            for (int c = 0; c < 22; ++c) xr[c] = xs[w0 + c];

            constexpr int FI6[9] = {0, 1, 2, 3, 4, 5, 6, 8, 9};           // fi[i] + 6
            constexpr int N0[9]  = {-54, -55, -56, -57, -58, -59, -60, -52, -53};
#pragma unroll
            for (int i = 0; i < 9; ++i) {
                float acc = 0.0f;
#pragma unroll
                for (int m = 0; m < 14; ++m) {
                    const int n  = N0[i] + 9 * m;
                    const int an = (n < 0) ? -n : n;
                    if (an <= 60) {                 // compile-time predicate after unroll
                        acc = fmaf(W[an], xr[FI6[i] + m], acc);
                    }
                }
                os[9 * tid + i] = acc;
            }
        }
        __syncwarp();

        // ---- Per-warp transpose store: 288 consecutive outputs -> coalesced float4 ----
        if (32 * wid < nk) {
            const size_t ob = (size_t)b * TOT_OUT + (size_t)9 * (kt + 32 * wid);
            const float4* src = reinterpret_cast<const float4*>(os + 288 * wid);
            float4* dst = reinterpret_cast<float4*>(out + ob);
#pragma unroll
            for (int v = lane; v < 72; v += 32) {   // 288 floats = 72 float4
                dst[v] = src[v];
            }
        }
    }
}

extern "C" void kernel_launch(void* const* d_in, const int* in_sizes, int n_in,
                              void* d_out, int out_size) {
    const float* in = (const float*)d_in[0];
    float* out = (float*)d_out;
    const int B = in_sizes[0] / T_IN;
    const int ntiles = B * TILES_PER_ROW;

    sp_weights_kernel<<<1, 64>>>();
    sp_resample_kernel<<<NCTA, 256>>>(in, out, ntiles);
}

// round 3
// speedup vs baseline: 2.8259x; 2.8259x over previous
#include <cuda_runtime.h>

// Kaldi LinearResample 16000 -> 14400, LPF_WIDTH=6 (polyphase, up=9, stride=10).
//   out[b, 9k+i] = sum_m w[i][m] * x[b, 10k + fi[i] + m],  x zero-padded outside [0,T)
//   fi[i] = {-6,-5,-4,-3,-2,-1,0,2,3};  tap weight depends only on n = 9*(fi[i]+m) - 10*i:
//   w(n) = (1+cos(0.0165*pi*|n|)) * sin(0.099*pi*|n|) * 9/(2*pi*|n|)  for 1<=|n|<=60,
//   w(0) = 0.891, w = 0 for |n|>60.  All 121 nonzero taps baked as compile-time
//   float literals (constexpr Taylor sin/cos) -> FFMA-imm, zero register cost.

#define T_IN        480000
#define TOT_K       48000
#define UP          9
#define TOT_OUT     (TOT_K * UP)
#define TILE_K      256
#define TILE_F      2576          // covers 10*255 + 22 + shift(<=2), float4 multiple
#define TILES_PER_ROW 188         // last tile nk = 128
#define NCTA        444           // 148 SM * 3 CTAs, persistent

// ---------------- compile-time weight table ----------------
constexpr double KPI = 3.14159265358979323846264338327950288;

constexpr double tsin(double x) {
    while (x >  KPI) x -= 2.0 * KPI;
    while (x < -KPI) x += 2.0 * KPI;
    double x2 = x * x, term = x, s = x;
    for (int k = 1; k <= 16; ++k) {
        term *= -x2 / (double)((2 * k) * (2 * k + 1));
        s += term;
    }
    return s;
}
constexpr double tcos(double x) { return tsin(KPI * 0.5 - x); }

struct WTab { float w[9][14]; };
constexpr WTab make_wtab() {
    WTab t{};
    constexpr int FI[9] = {-6, -5, -4, -3, -2, -1, 0, 2, 3};
    for (int i = 0; i < 9; ++i)
        for (int m = 0; m < 14; ++m) {
            int n = 9 * (FI[i] + m) - 10 * i;
            int an = n < 0 ? -n : n;
            double v = 0.0;
            if (an == 0)      v = 0.891;            // 2*lowpass_cutoff/orig_freq
            else if (an <= 60)
                v = (1.0 + tcos(0.0165 * KPI * an)) * tsin(0.099 * KPI * an)
                    * 9.0 / (2.0 * KPI * an);
            t.w[i][m] = (float)v;
        }
    return t;
}
// __device__ constexpr: initializer evaluated at compile time, device reads
// with constant indices fold to immediates (no memory traffic, no registers).
__device__ constexpr WTab WT = make_wtab();

// ---------------- cp.async helpers ----------------
__device__ __forceinline__ void cp_async16(float* smem_dst, const float* gsrc) {
    unsigned saddr = (unsigned)__cvta_generic_to_shared(smem_dst);
    asm volatile("cp.async.cg.shared.global [%0], [%1], 16;" :: "r"(saddr), "l"(gsrc));
}
#define CP_COMMIT() asm volatile("cp.async.commit_group;" ::: "memory")
#define CP_WAIT1()  asm volatile("cp.async.wait_group 1;"  ::: "memory")

// ---------------- staging (one tile into one smem buffer) ----------------
__device__ __forceinline__ void stage_tile(float* xs, const float* __restrict__ in,
                                           int t) {
    const int b  = t / TILES_PER_ROW;
    const int kt = (t - b * TILES_PER_ROW) * TILE_K;
    const float* rowin = in + (size_t)b * T_IN;
    const int gstart = 10 * kt - 6;
    const int g4 = gstart & ~3;

    if (g4 >= 0 && g4 + TILE_F <= T_IN) {
        // interior: pure async 16B copies
        for (int v = threadIdx.x; v < TILE_F / 4; v += 256)
            cp_async16(xs + 4 * v, rowin + g4 + 4 * v);
    } else {
        // edge (first/last tile of a row): guarded scalar path
        for (int v = threadIdx.x; v < TILE_F / 4; v += 256) {
            int g = g4 + 4 * v;
            float4 val;
            if (g >= 0 && g <= T_IN - 4) {
                val = *reinterpret_cast<const float4*>(rowin + g);
            } else {
                val.x = (g + 0 >= 0 && g + 0 < T_IN) ? rowin[g + 0] : 0.0f;
                val.y = (g + 1 >= 0 && g + 1 < T_IN) ? rowin[g + 1] : 0.0f;
                val.z = (g + 2 >= 0 && g + 2 < T_IN) ? rowin[g + 2] : 0.0f;
                val.w = (g + 3 >= 0 && g + 3 < T_IN) ? rowin[g + 3] : 0.0f;
            }
            *reinterpret_cast<float4*>(xs + 4 * v) = val;
        }
    }
}

__global__ __launch_bounds__(256, 3)
void sp_resample_kernel(const float* __restrict__ in, float* __restrict__ out,
                        int ntiles) {
    __shared__ float xs[2][TILE_F];
    __shared__ float os[TILE_K * UP];      // per-warp transpose buffer

    const int tid  = threadIdx.x;
    const int wid  = tid >> 5;
    const int lane = tid & 31;
    const int stride = gridDim.x;

    int t0 = blockIdx.x;
    if (t0 < ntiles) stage_tile(xs[0], in, t0);
    CP_COMMIT();

    int cur = 0;
    for (int t = t0; t < ntiles; t += stride) {
        __syncthreads();                       // (A) prev compute done reading xs[1-cur]
        int tn = t + stride;
        if (tn < ntiles) stage_tile(xs[1 - cur], in, tn);
        CP_COMMIT();
        CP_WAIT1();                            // xs[cur]'s cp.async group complete
        __syncthreads();                       // (B) data visible to all warps

        const int b  = t / TILES_PER_ROW;
        const int kt = (t - b * TILES_PER_ROW) * TILE_K;
        const int nk = min(TILE_K, TOT_K - kt);        // 256 or 128 (warp multiple)
        const int gstart = 10 * kt - 6;
        const int shift  = gstart - (gstart & ~3);     // 0 or 2 (gstart even)
        const float* xb = xs[cur];

        if (tid < nk) {
            float2 xr2[11];
            const int w0 = 10 * tid + shift;           // even -> aligned float2
#pragma unroll
            for (int c = 0; c < 11; ++c)
                xr2[c] = *reinterpret_cast<const float2*>(xb + w0 + 2 * c);
#define XR(c) (((c) & 1) ? xr2[(c) >> 1].y : xr2[(c) >> 1].x)

            constexpr int FI6[9] = {0, 1, 2, 3, 4, 5, 6, 8, 9};
            constexpr int N0[9]  = {-54, -55, -56, -57, -58, -59, -60, -52, -53};
#pragma unroll
            for (int i = 0; i < 9; ++i) {
                float acc = 0.0f;
#pragma unroll
                for (int m = 0; m < 14; ++m) {
                    const int n  = N0[i] + 9 * m;
                    const int an = (n < 0) ? -n : n;
                    if (an <= 60) {                    // pruned at compile time
                        acc = fmaf(WT.w[i][m], XR(FI6[i] + m), acc);
                    }
                }
                os[9 * tid + i] = acc;
            }
#undef XR
        }
        __syncwarp();

        if (32 * wid < nk) {
            const size_t ob = (size_t)b * TOT_OUT + (size_t)9 * (kt + 32 * wid);
            const float4* src = reinterpret_cast<const float4*>(os + 288 * wid);
            float4* dst = reinterpret_cast<float4*>(out + ob);
#pragma unroll
            for (int v = lane; v < 72; v += 32)        // 288 floats = 72 float4
                dst[v] = src[v];
        }
        cur ^= 1;
    }
}

extern "C" void kernel_launch(void* const* d_in, const int* in_sizes, int n_in,
                              void* d_out, int out_size) {
    const float* in = (const float*)d_in[0];
    float* out = (float*)d_out;
    const int B = in_sizes[0] / T_IN;
    const int ntiles = B * TILES_PER_ROW;
    sp_resample_kernel<<<NCTA, 256>>>(in, out, ntiles);
}

// round 4
// speedup vs baseline: 2.8530x; 1.0096x over previous
#include <cuda_runtime.h>

// Kaldi LinearResample 16000 -> 14400, LPF_WIDTH=6 (polyphase, up=9, stride=10).
//   out[b, 9k+i] = sum_m w[i][m] * x[b, 10k + fi[i] + m],  x zero-padded outside [0,T)
//   fi[i] = {-6,-5,-4,-3,-2,-1,0,2,3};  tap weight depends only on n = 9*(fi[i]+m) - 10*i:
//   w(n) = (1+cos(0.0165*pi*|n|)) * sin(0.099*pi*|n|) * 9/(2*pi*|n|)  for 1<=|n|<=60,
//   w(0) = 0.891, w = 0 for |n|>60.  All 121 nonzero taps baked as compile-time
//   float literals (constexpr Taylor sin/cos) -> FFMA-imm, zero register cost.

#define T_IN        480000
#define TOT_K       48000
#define UP          9
#define TOT_OUT     (TOT_K * UP)
#define TILE_K      256
#define TILE_F      2576          // covers 10*255 + 22 + shift(<=2), float4 multiple
#define TILES_PER_ROW 188         // last tile nk = 128
#define NCTA        888           // 148 SM * 6 CTAs, persistent

// ---------------- compile-time weight table ----------------
constexpr double KPI = 3.14159265358979323846264338327950288;

constexpr double tsin(double x) {
    while (x >  KPI) x -= 2.0 * KPI;
    while (x < -KPI) x += 2.0 * KPI;
    double x2 = x * x, term = x, s = x;
    for (int k = 1; k <= 16; ++k) {
        term *= -x2 / (double)((2 * k) * (2 * k + 1));
        s += term;
    }
    return s;
}
constexpr double tcos(double x) { return tsin(KPI * 0.5 - x); }

struct WTab { float w[9][14]; };
constexpr WTab make_wtab() {
    WTab t{};
    constexpr int FI[9] = {-6, -5, -4, -3, -2, -1, 0, 2, 3};
    for (int i = 0; i < 9; ++i)
        for (int m = 0; m < 14; ++m) {
            int n = 9 * (FI[i] + m) - 10 * i;
            int an = n < 0 ? -n : n;
            double v = 0.0;
            if (an == 0)      v = 0.891;            // 2*lowpass_cutoff/orig_freq
            else if (an <= 60)
                v = (1.0 + tcos(0.0165 * KPI * an)) * tsin(0.099 * KPI * an)
                    * 9.0 / (2.0 * KPI * an);
            t.w[i][m] = (float)v;
        }
    return t;
}
// __device__ constexpr: initializer evaluated at compile time, device reads
// with constant indices fold to immediates (no memory traffic, no registers).
__device__ constexpr WTab WT = make_wtab();

// ---------------- cp.async helpers ----------------
__device__ __forceinline__ void cp_async16(float* smem_dst, const float* gsrc) {
    unsigned saddr = (unsigned)__cvta_generic_to_shared(smem_dst);
    asm volatile("cp.async.cg.shared.global [%0], [%1], 16;" :: "r"(saddr), "l"(gsrc));
}
#define CP_COMMIT() asm volatile("cp.async.commit_group;" ::: "memory")
#define CP_WAIT1()  asm volatile("cp.async.wait_group 1;"  ::: "memory")

// ---------------- staging (one tile into one smem buffer) ----------------
__device__ __forceinline__ void stage_tile(float* xs, const float* __restrict__ in,
                                           int t) {
    const int b  = t / TILES_PER_ROW;
    const int kt = (t - b * TILES_PER_ROW) * TILE_K;
    const float* rowin = in + (size_t)b * T_IN;
    const int gstart = 10 * kt - 6;
    const int g4 = gstart & ~3;

    if (g4 >= 0 && g4 + TILE_F <= T_IN) {
        // interior: pure async 16B copies
        for (int v = threadIdx.x; v < TILE_F / 4; v += 256)
            cp_async16(xs + 4 * v, rowin + g4 + 4 * v);
    } else {
        // edge (first/last tile of a row): guarded scalar path
        for (int v = threadIdx.x; v < TILE_F / 4; v += 256) {
            int g = g4 + 4 * v;
            float4 val;
            if (g >= 0 && g <= T_IN - 4) {
                val = *reinterpret_cast<const float4*>(rowin + g);
            } else {
                val.x = (g + 0 >= 0 && g + 0 < T_IN) ? rowin[g + 0] : 0.0f;
                val.y = (g + 1 >= 0 && g + 1 < T_IN) ? rowin[g + 1] : 0.0f;
                val.z = (g + 2 >= 0 && g + 2 < T_IN) ? rowin[g + 2] : 0.0f;
                val.w = (g + 3 >= 0 && g + 3 < T_IN) ? rowin[g + 3] : 0.0f;
            }
            *reinterpret_cast<float4*>(xs + 4 * v) = val;
        }
    }
}

__global__ __launch_bounds__(256, 6)
void sp_resample_kernel(const float* __restrict__ in, float* __restrict__ out,
                        int ntiles) {
    __shared__ float xs[2][TILE_F];
    __shared__ float os[TILE_K * UP];      // per-warp transpose buffer

    const int tid  = threadIdx.x;
    const int wid  = tid >> 5;
    const int lane = tid & 31;
    const int stride = gridDim.x;

    int t0 = blockIdx.x;
    if (t0 < ntiles) stage_tile(xs[0], in, t0);
    CP_COMMIT();

    int cur = 0;
    for (int t = t0; t < ntiles; t += stride) {
        __syncthreads();                       // (A) prev compute done reading xs[1-cur]
        int tn = t + stride;
        if (tn < ntiles) stage_tile(xs[1 - cur], in, tn);
        CP_COMMIT();
        CP_WAIT1();                            // xs[cur]'s cp.async group complete
        __syncthreads();                       // (B) data visible to all warps

        const int b  = t / TILES_PER_ROW;
        const int kt = (t - b * TILES_PER_ROW) * TILE_K;
        const int nk = min(TILE_K, TOT_K - kt);        // 256 or 128 (warp multiple)
        const int gstart = 10 * kt - 6;
        const int shift  = gstart - (gstart & ~3);     // 0 or 2 (gstart even)
        const float* xb = xs[cur];

        if (tid < nk) {
            float2 xr2[11];
            const int w0 = 10 * tid + shift;           // even -> aligned float2
#pragma unroll
            for (int c = 0; c < 11; ++c)
                xr2[c] = *reinterpret_cast<const float2*>(xb + w0 + 2 * c);
#define XR(c) (((c) & 1) ? xr2[(c) >> 1].y : xr2[(c) >> 1].x)

            constexpr int FI6[9] = {0, 1, 2, 3, 4, 5, 6, 8, 9};
            constexpr int N0[9]  = {-54, -55, -56, -57, -58, -59, -60, -52, -53};
#pragma unroll
            for (int i = 0; i < 9; ++i) {
                float acc = 0.0f;
#pragma unroll
                for (int m = 0; m < 14; ++m) {
                    const int n  = N0[i] + 9 * m;
                    const int an = (n < 0) ? -n : n;
                    if (an <= 60) {                    // pruned at compile time
                        acc = fmaf(WT.w[i][m], XR(FI6[i] + m), acc);
                    }
                }
                os[9 * tid + i] = acc;
            }
#undef XR
        }
        __syncwarp();

        if (32 * wid < nk) {
            const size_t ob = (size_t)b * TOT_OUT + (size_t)9 * (kt + 32 * wid);
            const float4* src = reinterpret_cast<const float4*>(os + 288 * wid);
            float4* dst = reinterpret_cast<float4*>(out + ob);
#pragma unroll
            for (int v = lane; v < 72; v += 32)        // 288 floats = 72 float4
                dst[v] = src[v];
        }
        cur ^= 1;
    }
}

extern "C" void kernel_launch(void* const* d_in, const int* in_sizes, int n_in,
                              void* d_out, int out_size) {
    const float* in = (const float*)d_in[0];
    float* out = (float*)d_out;
    const int B = in_sizes[0] / T_IN;
    const int ntiles = B * TILES_PER_ROW;
    sp_resample_kernel<<<NCTA, 256>>>(in, out, ntiles);
}

// round 5
// speedup vs baseline: 2.8721x; 1.0067x over previous
#include <cuda_runtime.h>

// Kaldi LinearResample 16000 -> 14400, LPF_WIDTH=6 (polyphase, up=9, stride=10).
//   out[b, 9k+i] = sum_m w[i][m] * x[b, 10k + fi[i] + m],  x zero-padded outside [0,T)
//   fi[i] = {-6,-5,-4,-3,-2,-1,0,2,3};  tap weight depends only on n = 9*(fi[i]+m) - 10*i.
//   All 121 nonzero taps baked as compile-time float literals -> FFMA-imm.

#define T_IN        480000
#define TOT_K       48000
#define UP          9
#define TOT_OUT     (TOT_K * UP)
#define TILE_K      384
#define NTHREADS    384
#define TILE_F      3856          // 10*383 + 22 + shift(<=2), float4 multiple
#define TILES_PER_ROW 125         // 48000 / 384 exactly -> every tile full
#define NCTA        592           // 148 SM * 4 CTAs, persistent

// ---------------- compile-time weight table ----------------
constexpr double KPI = 3.14159265358979323846264338327950288;

constexpr double tsin(double x) {
    while (x >  KPI) x -= 2.0 * KPI;
    while (x < -KPI) x += 2.0 * KPI;
    double x2 = x * x, term = x, s = x;
    for (int k = 1; k <= 16; ++k) {
        term *= -x2 / (double)((2 * k) * (2 * k + 1));
        s += term;
    }
    return s;
}
constexpr double tcos(double x) { return tsin(KPI * 0.5 - x); }

struct WTab { float w[9][14]; };
constexpr WTab make_wtab() {
    WTab t{};
    constexpr int FI[9] = {-6, -5, -4, -3, -2, -1, 0, 2, 3};
    for (int i = 0; i < 9; ++i)
        for (int m = 0; m < 14; ++m) {
            int n = 9 * (FI[i] + m) - 10 * i;
            int an = n < 0 ? -n : n;
            double v = 0.0;
            if (an == 0)      v = 0.891;            // 2*lowpass_cutoff/orig_freq
            else if (an <= 60)
                v = (1.0 + tcos(0.0165 * KPI * an)) * tsin(0.099 * KPI * an)
                    * 9.0 / (2.0 * KPI * an);
            t.w[i][m] = (float)v;
        }
    return t;
}
__device__ constexpr WTab WT = make_wtab();

// ---------------- cp.async helpers ----------------
__device__ __forceinline__ void cp_async16(float* smem_dst, const float* gsrc) {
    unsigned saddr = (unsigned)__cvta_generic_to_shared(smem_dst);
    asm volatile("cp.async.cg.shared.global [%0], [%1], 16;" :: "r"(saddr), "l"(gsrc));
}
#define CP_COMMIT() asm volatile("cp.async.commit_group;" ::: "memory")
#define CP_WAIT1()  asm volatile("cp.async.wait_group 1;"  ::: "memory")

// ---------------- staging (one tile into one smem buffer) ----------------
__device__ __forceinline__ void stage_tile(float* xs, const float* __restrict__ in,
                                           int t) {
    const int b  = t / TILES_PER_ROW;
    const int kt = (t - b * TILES_PER_ROW) * TILE_K;
    const float* rowin = in + (size_t)b * T_IN;
    const int gstart = 10 * kt - 6;
    const int g4 = gstart & ~3;

    if (g4 >= 0 && g4 + TILE_F <= T_IN) {
        // interior (123 of 125 tiles per row): pure async 16B copies
        for (int v = threadIdx.x; v < TILE_F / 4; v += NTHREADS)
            cp_async16(xs + 4 * v, rowin + g4 + 4 * v);
    } else {
        // edge tile: guarded scalar path with zero padding
        for (int v = threadIdx.x; v < TILE_F / 4; v += NTHREADS) {
            int g = g4 + 4 * v;
            float4 val;
            if (g >= 0 && g <= T_IN - 4) {
                val = *reinterpret_cast<const float4*>(rowin + g);
            } else {
                val.x = (g + 0 >= 0 && g + 0 < T_IN) ? rowin[g + 0] : 0.0f;
                val.y = (g + 1 >= 0 && g + 1 < T_IN) ? rowin[g + 1] : 0.0f;
                val.z = (g + 2 >= 0 && g + 2 < T_IN) ? rowin[g + 2] : 0.0f;
                val.w = (g + 3 >= 0 && g + 3 < T_IN) ? rowin[g + 3] : 0.0f;
            }
            *reinterpret_cast<float4*>(xs + 4 * v) = val;
        }
    }
}

__global__ __launch_bounds__(NTHREADS, 4)
void sp_resample_kernel(const float* __restrict__ in, float* __restrict__ out,
                        int ntiles) {
    __shared__ float xs[2][TILE_F];
    __shared__ float os[TILE_K * UP];      // warp-private 288-float blocks

    const int tid  = threadIdx.x;
    const int wid  = tid >> 5;
    const int lane = tid & 31;
    const int stride = gridDim.x;

    int t0 = blockIdx.x;
    if (t0 < ntiles) stage_tile(xs[0], in, t0);
    CP_COMMIT();

    int cur = 0;
    for (int t = t0; t < ntiles; t += stride) {
        __syncthreads();                       // prev compute done reading xs[1-cur]
        int tn = t + stride;
        if (tn < ntiles) stage_tile(xs[1 - cur], in, tn);
        CP_COMMIT();
        CP_WAIT1();                            // xs[cur]'s cp.async group complete
        __syncthreads();                       // data visible to all warps

        const int b  = t / TILES_PER_ROW;
        const int kt = (t - b * TILES_PER_ROW) * TILE_K;
        const int gstart = 10 * kt - 6;
        const int shift  = gstart & 3;                 // 0 or 2 (gstart even)
        const float* xb = xs[cur];

        {
            float2 xr2[11];
            const int w0 = 10 * tid + shift;           // even -> aligned float2
#pragma unroll
            for (int c = 0; c < 11; ++c)
                xr2[c] = *reinterpret_cast<const float2*>(xb + w0 + 2 * c);
#define XR(c) (((c) & 1) ? xr2[(c) >> 1].y : xr2[(c) >> 1].x)

            constexpr int FI6[9] = {0, 1, 2, 3, 4, 5, 6, 8, 9};
            constexpr int N0[9]  = {-54, -55, -56, -57, -58, -59, -60, -52, -53};
#pragma unroll
            for (int i = 0; i < 9; ++i) {
                float acc = 0.0f;
#pragma unroll
                for (int m = 0; m < 14; ++m) {
                    const int n  = N0[i] + 9 * m;
                    const int an = (n < 0) ? -n : n;
                    if (an <= 60) {                    // pruned at compile time
                        acc = fmaf(WT.w[i][m], XR(FI6[i] + m), acc);
                    }
                }
                os[9 * tid + i] = acc;
            }
#undef XR
        }
        __syncwarp();

        {
            const size_t ob = (size_t)b * TOT_OUT + (size_t)9 * (kt + 32 * wid);
            const float4* src = reinterpret_cast<const float4*>(os + 288 * wid);
            float4* dst = reinterpret_cast<float4*>(out + ob);
#pragma unroll
            for (int v = lane; v < 72; v += 32)        // 288 floats = 72 float4
                dst[v] = src[v];
        }
        cur ^= 1;
    }
}

extern "C" void kernel_launch(void* const* d_in, const int* in_sizes, int n_in,
                              void* d_out, int out_size) {
    const float* in = (const float*)d_in[0];
    float* out = (float*)d_out;
    const int B = in_sizes[0] / T_IN;
    const int ntiles = B * TILES_PER_ROW;
    sp_resample_kernel<<<NCTA, NTHREADS>>>(in, out, ntiles);
}